// round 15
// baseline (speedup 1.0000x reference)
#include <cuda_runtime.h>
#include <cuda_bf16.h>
#include <cstdint>
#include <math.h>

// Problem constants
#define NB     4
#define SQ     2048
#define DIMM   1024
#define INNERD 1024
#define MTOK   (NB * SQ)          // 8192
#define KCH    16                 // k per pipeline chunk

typedef __nv_bfloat16  bf16;
typedef __nv_bfloat162 bf162;

// ---------------- scratch (allocation-free rule: __device__ globals) ----------------
__device__ __align__(256) float g_qkv [(size_t)MTOK * 3 * INNERD];   // 96 MB fp32
__device__ __align__(256) float g_att [(size_t)MTOK * SQ];           // 64 MB fp32
__device__ __align__(256) bf16  g_x2  [(size_t)MTOK * 3 * DIMM];     // A-style split of x
__device__ __align__(256) bf16  g_q2  [(size_t)MTOK * 3 * INNERD];   // A-style split of Q
__device__ __align__(256) bf16  g_k2  [(size_t)MTOK * 3 * INNERD];   // B-style split of K
__device__ __align__(256) bf16  g_v2  [(size_t)NB * INNERD * 3 * SQ];// B-style transposed V
__device__ __align__(256) bf16  g_at2 [(size_t)MTOK * 3 * SQ];       // A-style split of attn
__device__ __align__(256) bf16  g_ao2 [(size_t)MTOK * 3 * INNERD];   // A-style split of attn@V
__device__ __align__(256) bf16  g_wq2 [(size_t)(3 * INNERD) * (3 * DIMM)]; // [3072, 3072]
__device__ __align__(256) bf16  g_wo2 [(size_t)DIMM * 3 * INNERD];   // [1024, 3072]

// ---------------- helpers ----------------
__device__ __forceinline__ uint32_t smem_u32(const void* p) {
    uint32_t a;
    asm("{ .reg .u64 t; cvta.to.shared.u64 t, %1; cvt.u32.u64 %0, t; }" : "=r"(a) : "l"(p));
    return a;
}
__device__ __forceinline__ void cpa16(uint32_t dst, const void* src) {
    asm volatile("cp.async.cg.shared.global [%0], [%1], 16;" :: "r"(dst), "l"(src));
}
__device__ __forceinline__ void cpa_commit() { asm volatile("cp.async.commit_group;"); }
__device__ __forceinline__ void cpa_wait1()  { asm volatile("cp.async.wait_group 1;" ::: "memory"); }

__device__ __forceinline__ void mma16(float* c, const unsigned* a, unsigned b0, unsigned b1) {
    asm volatile(
        "mma.sync.aligned.m16n8k16.row.col.f32.bf16.bf16.f32 "
        "{%0,%1,%2,%3}, {%4,%5,%6,%7}, {%8,%9}, {%0,%1,%2,%3};\n"
        : "+f"(c[0]), "+f"(c[1]), "+f"(c[2]), "+f"(c[3])
        : "r"(a[0]), "r"(a[1]), "r"(a[2]), "r"(a[3]), "r"(b0), "r"(b1));
}
__device__ __forceinline__ void ldsm4(uint32_t addr, unsigned* r) {
    asm volatile("ldmatrix.sync.aligned.m8n8.x4.shared.b16 {%0,%1,%2,%3}, [%4];"
        : "=r"(r[0]), "=r"(r[1]), "=r"(r[2]), "=r"(r[3]) : "r"(addr));
}
__device__ __forceinline__ void splitf2(float x, float y, bf162& h, bf162& l) {
    h = __floats2bfloat162_rn(x, y);
    l = __floats2bfloat162_rn(x - __low2float(h), y - __high2float(h));
}

// ---------------- barrier-free warp-private bf16 NT GEMM ----------------
// C = alpha * A @ B^T (+bias).  CTA tile 128(M) x 64(N), 64 threads = 2 warps,
// warp tile 64x64.  Each warp cp.asyncs its own A rows AND its own duplicate of
// the B tile into warp-private SMEM; consumers are the same warp => only
// cp.async.wait_group + __syncwarp needed, NO __syncthreads in the mainloop.
// SMEM: 3 stages x 2 warps x (A 2KB | B 2KB) = 24KB static.
// 32B rows; swizzle q ^ ((row>>2)&1) is conflict-free for fill and ldsm.
template <int EPI>
__global__ __launch_bounds__(64, 4)
void gemm_nt(const bf16* __restrict__ A, const bf16* __restrict__ B,
             float* __restrict__ C, bf16* __restrict__ C2,
             const float* __restrict__ bias,
             int Kp, int lda, int ldb, int ldc, int segN,
             long long bA, long long bB, long long bC, float alpha)
{
    __shared__ __align__(128) char smem[3 * 8192];   // [stage][warp][A|B]
    const uint32_t u0 = smem_u32(smem);

    const int tid = threadIdx.x;
    const int warp = tid >> 5, lane = tid & 31;      // warp = m-half
    const int m0 = blockIdx.y * 128, n0 = blockIdx.x * 64;
    A += (long long)blockIdx.z * bA;
    B += (long long)blockIdx.z * bB;

    // ---- fill mapping: lane -> (row = (lane>>1) + 16i, 16B-half = lane&1) ----
    const int fr = lane >> 1, fg = lane & 1;
    const bf16* pA[4]; const bf16* pB[4];
    uint32_t oX[4];
    #pragma unroll
    for (int i = 0; i < 4; i++) {
        int r = fr + 16 * i;
        pA[i] = A + (long long)(m0 + warp * 64 + r) * lda + 8 * fg;
        pB[i] = B + (long long)(n0 + r) * ldb + 8 * fg;
        oX[i] = r * 32 + (((unsigned)(fg ^ ((r >> 2) & 1))) << 4);
    }
    const uint32_t wb = u0 + warp * 4096;            // + stage*8192; B at +2048

#define FILL(S)                                                           \
    {                                                                     \
        const uint32_t da_ = wb + (S) * 8192, db_ = da_ + 2048;           \
        _Pragma("unroll")                                                 \
        for (int i_ = 0; i_ < 4; i_++) cpa16(da_ + oX[i_], pA[i_]);       \
        _Pragma("unroll")                                                 \
        for (int i_ = 0; i_ < 4; i_++) cpa16(db_ + oX[i_], pB[i_]);       \
        cpa_commit();                                                     \
        _Pragma("unroll")                                                 \
        for (int i_ = 0; i_ < 4; i_++) { pA[i_] += KCH; pB[i_] += KCH; }  \
    }

    // ---- ldsm per-tile offsets (tile t = 16 rows; row = t*16 + (lane&15)) ----
    uint32_t toff[4];
    {
        int rl = lane & 15, lg = lane >> 4;
        #pragma unroll
        for (int t = 0; t < 4; t++) {
            int r = t * 16 + rl;
            toff[t] = r * 32 + (((unsigned)(lg ^ ((r >> 2) & 1))) << 4);
        }
    }

#define LDSM_CHUNK(S, FA, FB)                                             \
    {                                                                     \
        const uint32_t la_ = wb + (S) * 8192, lbb_ = la_ + 2048;          \
        _Pragma("unroll")                                                 \
        for (int t_ = 0; t_ < 4; t_++) ldsm4(la_ + toff[t_], FA[t_]);     \
        _Pragma("unroll")                                                 \
        for (int t_ = 0; t_ < 4; t_++) ldsm4(lbb_ + toff[t_], FB[t_]);    \
    }

#define MMAS(FA, FB)                                                      \
    _Pragma("unroll")                                                     \
    for (int mi_ = 0; mi_ < 4; mi_++)                                     \
        _Pragma("unroll")                                                 \
        for (int p_ = 0; p_ < 4; p_++) {                                  \
            mma16(acc[mi_][2 * p_    ], FA[mi_], FB[p_][0], FB[p_][2]);   \
            mma16(acc[mi_][2 * p_ + 1], FA[mi_], FB[p_][1], FB[p_][3]);   \
        }

    float acc[4][8][4] = {};
    unsigned fA0[4][4], fB0[4][4], fA1[4][4], fB1[4][4];

    const int nch = Kp / KCH;    // 192 or 384: divisible by 6

    FILL(0)
    FILL(1)
    cpa_wait1(); __syncwarp();
    LDSM_CHUNK(0, fA0, fB0)

    // step: fill(c+2) -> mma(c) -> wait(c+1)+syncwarp -> ldsm(c+1)
#define STEP(LD_S, FI_S, FCA, FCB, FNA, FNB)                              \
    {                                                                     \
        if (c + 2 < nch) FILL(FI_S) else cpa_commit();                    \
        MMAS(FCA, FCB)                                                    \
        if (c + 1 < nch) {                                                \
            cpa_wait1(); __syncwarp();                                    \
            LDSM_CHUNK(LD_S, FNA, FNB)                                    \
        }                                                                 \
        c++;                                                              \
    }

    int c = 0;
    while (c < nch) {
        STEP(1, 2, fA0, fB0, fA1, fB1)
        STEP(2, 0, fA1, fB1, fA0, fB0)
        STEP(0, 1, fA0, fB0, fA1, fB1)
        STEP(1, 2, fA1, fB1, fA0, fB0)
        STEP(2, 0, fA0, fB0, fA1, fB1)
        STEP(0, 1, fA1, fB1, fA0, fB0)
    }
#undef STEP
#undef MMAS
#undef LDSM_CHUNK
#undef FILL

    // ---- epilogue ----
    const int gid = lane >> 2, tig = lane & 3;
    if (EPI == 0) {
        C += (long long)blockIdx.z * bC;
        #pragma unroll
        for (int mi = 0; mi < 4; mi++) {
            #pragma unroll
            for (int ni = 0; ni < 8; ni++) {
                const int col  = n0 + ni * 8 + 2 * tig;
                const int row0 = m0 + warp * 64 + mi * 16 + gid;
                float b0v = bias ? bias[col]     : 0.f;
                float b1v = bias ? bias[col + 1] : 0.f;
                float2 v0 = make_float2(acc[mi][ni][0] * alpha + b0v,
                                        acc[mi][ni][1] * alpha + b1v);
                float2 v1 = make_float2(acc[mi][ni][2] * alpha + b0v,
                                        acc[mi][ni][3] * alpha + b1v);
                *(float2*)(C + (long long)row0 * ldc + col)       = v0;
                *(float2*)(C + (long long)(row0 + 8) * ldc + col) = v1;
            }
        }
    } else {
        C2 += (long long)blockIdx.z * bC;
        #pragma unroll
        for (int mi = 0; mi < 4; mi++) {
            #pragma unroll
            for (int ni = 0; ni < 8; ni++) {
                const int col  = n0 + ni * 8 + 2 * tig;
                const int row0 = m0 + warp * 64 + mi * 16 + gid;
                bf162 h2, l2;
                splitf2(acc[mi][ni][0], acc[mi][ni][1], h2, l2);
                bf16* p0 = C2 + (long long)row0 * ldc + col;
                *(bf162*)p0            = h2;
                *(bf162*)(p0 + segN)   = l2;
                *(bf162*)(p0 + 2*segN) = h2;
                splitf2(acc[mi][ni][2], acc[mi][ni][3], h2, l2);
                bf16* p1 = C2 + (long long)(row0 + 8) * ldc + col;
                *(bf162*)p1            = h2;
                *(bf162*)(p1 + segN)   = l2;
                *(bf162*)(p1 + 2*segN) = h2;
            }
        }
    }
}

// ---------------- split kernels ----------------
// Row-major split: in fp32 [R,C] (ld ldin) -> out bf16 [R,3C].
// STYLE 0 (A-side): [h | l | h]   STYLE 1 (B-side): [h | h | l]
template <int STYLE>
__global__ __launch_bounds__(256)
void split_rm(const float* __restrict__ in, bf16* __restrict__ out, int C, int ldin)
{
    const int r = blockIdx.y;
    const int j = (blockIdx.x * 256 + threadIdx.x) * 2;
    float2 v = *(const float2*)(in + (long long)r * ldin + j);
    bf162 h2, l2;
    splitf2(v.x, v.y, h2, l2);
    bf16* o = out + (long long)r * 3 * C + j;
    *(bf162*)o = h2;
    if (STYLE == 0) { *(bf162*)(o + C) = l2; *(bf162*)(o + 2 * C) = h2; }
    else            { *(bf162*)(o + C) = h2; *(bf162*)(o + 2 * C) = l2; }
}

// Transpose split (B-style): in fp32 [Krows, N] (ld ldin) -> out bf16 [N, 3*Kd].
__global__ __launch_bounds__(256)
void split_tr(const float* __restrict__ in, bf16* __restrict__ out,
              int ldin, int Kd, long long bIn, long long bOut)
{
    __shared__ float t[32][33];
    in  += (long long)blockIdx.z * bIn;
    out += (long long)blockIdx.z * bOut;
    const int k0 = blockIdx.y * 32, nn0 = blockIdx.x * 32;
    const int tx = threadIdx.x & 31, ty = threadIdx.x >> 5;
    #pragma unroll
    for (int i = 0; i < 4; i++)
        t[ty + 8 * i][tx] = in[(long long)(k0 + ty + 8 * i) * ldin + nn0 + tx];
    __syncthreads();
    #pragma unroll
    for (int i = 0; i < 4; i++) {
        float v = t[tx][ty + 8 * i];
        bf16 h = __float2bfloat16(v);
        bf16 l = __float2bfloat16(v - __bfloat162float(h));
        bf16* o = out + (long long)(nn0 + ty + 8 * i) * (3 * Kd) + k0 + tx;
        o[0] = h; o[Kd] = h; o[2 * Kd] = l;
    }
}

// ---------------- softmax + A-style split (fp32 [8192,2048] -> bf16 [8192,6144]) ----------------
__global__ __launch_bounds__(256)
void softmax_split(const float* __restrict__ att, bf16* __restrict__ out)
{
    const long long r = blockIdx.x;
    const float* row = att + r * 2048;
    bf16* orow = out + r * 6144;
    const int t = threadIdx.x;
    float2 v[4];
    float mx = -1e30f;
    #pragma unroll
    for (int j = 0; j < 4; j++) {
        v[j] = *(const float2*)(row + 2 * (t + j * 256));
        mx = fmaxf(mx, fmaxf(v[j].x, v[j].y));
    }
    __shared__ float red[256];
    red[t] = mx; __syncthreads();
    for (int s = 128; s > 0; s >>= 1) {
        if (t < s) red[t] = fmaxf(red[t], red[t + s]);
        __syncthreads();
    }
    mx = red[0]; __syncthreads();
    float sum = 0.f;
    #pragma unroll
    for (int j = 0; j < 4; j++) {
        v[j].x = __expf(v[j].x - mx);
        v[j].y = __expf(v[j].y - mx);
        sum += v[j].x + v[j].y;
    }
    red[t] = sum; __syncthreads();
    for (int s = 128; s > 0; s >>= 1) {
        if (t < s) red[t] += red[t + s];
        __syncthreads();
    }
    const float inv = 1.f / red[0];
    #pragma unroll
    for (int j = 0; j < 4; j++) {
        const int idx = 2 * (t + j * 256);
        bf162 h2, l2;
        splitf2(v[j].x * inv, v[j].y * inv, h2, l2);
        *(bf162*)(orow + idx)        = h2;
        *(bf162*)(orow + 2048 + idx) = l2;
        *(bf162*)(orow + 4096 + idx) = h2;
    }
}

// ---------------- launch ----------------
extern "C" void kernel_launch(void* const* d_in, const int* in_sizes, int n_in,
                              void* d_out, int out_size)
{
    const float* x    = (const float*)d_in[0];   // [4, 2048, 1024]
    const float* Wqkv = (const float*)d_in[1];   // [1024, 3072]
    const float* Wout = (const float*)d_in[2];   // [1024, 1024]
    const float* bout = (const float*)d_in[3];   // [1024]
    float* out = (float*)d_out;                  // [4, 2048, 1024]

    float *qkv, *att;
    bf16 *x2, *q2, *k2, *v2, *at2, *ao2, *wq2, *wo2;
    cudaGetSymbolAddress((void**)&qkv, g_qkv);
    cudaGetSymbolAddress((void**)&att, g_att);
    cudaGetSymbolAddress((void**)&x2,  g_x2);
    cudaGetSymbolAddress((void**)&q2,  g_q2);
    cudaGetSymbolAddress((void**)&k2,  g_k2);
    cudaGetSymbolAddress((void**)&v2,  g_v2);
    cudaGetSymbolAddress((void**)&at2, g_at2);
    cudaGetSymbolAddress((void**)&ao2, g_ao2);
    cudaGetSymbolAddress((void**)&wq2, g_wq2);
    cudaGetSymbolAddress((void**)&wo2, g_wo2);

    // 0) operand splits of the inputs
    split_rm<0><<<dim3(DIMM / 512, MTOK), 256>>>(x, x2, DIMM, DIMM);
    split_tr<<<dim3(3 * INNERD / 32, DIMM / 32, 1), 256>>>(Wqkv, wq2, 3 * INNERD, DIMM, 0, 0);
    split_tr<<<dim3(DIMM / 32, INNERD / 32, 1), 256>>>(Wout, wo2, DIMM, INNERD, 0, 0);

    // 1) qkv = x @ Wqkv          (M=8192, N=3072, K'=3072)
    gemm_nt<0><<<dim3(3 * INNERD / 64, MTOK / 128, 1), 64>>>(
        x2, wq2, qkv, nullptr, nullptr,
        3 * DIMM, 3 * DIMM, 3 * DIMM, 3 * INNERD, 0, 0, 0, 0, 1.f);

    // 2) splits of Q, K, V from qkv
    split_rm<0><<<dim3(2, MTOK), 256>>>(qkv,        q2, INNERD, 3 * INNERD);
    split_rm<1><<<dim3(2, MTOK), 256>>>(qkv + 1024, k2, INNERD, 3 * INNERD);
    split_tr<<<dim3(INNERD / 32, SQ / 32, NB), 256>>>(
        qkv + 2048, v2, 3 * INNERD, SQ,
        (long long)SQ * 3 * INNERD, (long long)INNERD * 3 * SQ);

    // 3) att = 0.125 * Q @ K^T   (per batch, M=N=2048, K'=3072)
    gemm_nt<0><<<dim3(SQ / 64, SQ / 128, NB), 64>>>(
        q2, k2, att, nullptr, nullptr,
        3 * INNERD, 3 * INNERD, 3 * INNERD, SQ, 0,
        (long long)SQ * 3 * INNERD, (long long)SQ * 3 * INNERD,
        (long long)SQ * SQ, 0.125f);

    // 4) softmax rows + A-style split
    softmax_split<<<MTOK, 256>>>(att, at2);

    // 5) ao2 = split(attn @ V)   (per batch, M=2048, N=1024, K'=6144; split epilogue)
    gemm_nt<1><<<dim3(INNERD / 64, SQ / 128, NB), 64>>>(
        at2, v2, nullptr, ao2, nullptr,
        3 * SQ, 3 * SQ, 3 * SQ, 3 * INNERD, INNERD,
        (long long)SQ * 3 * SQ, (long long)INNERD * 3 * SQ,
        (long long)SQ * 3 * INNERD, 1.f);

    // 6) out = ao @ Wout + bias  (M=8192, N=1024, K'=3072)
    gemm_nt<0><<<dim3(DIMM / 64, MTOK / 128, 1), 64>>>(
        ao2, wo2, out, nullptr, bout,
        3 * INNERD, 3 * INNERD, 3 * INNERD, DIMM, 0, 0, 0, 0, 1.f);
}

// round 16
// speedup vs baseline: 1.6176x; 1.6176x over previous
#include <cuda_runtime.h>
#include <cuda_bf16.h>
#include <cstdint>
#include <math.h>

// Problem constants
#define NB     4
#define SQ     2048
#define DIMM   1024
#define INNERD 1024
#define MTOK   (NB * SQ)          // 8192

typedef __nv_bfloat16  bf16;
typedef __nv_bfloat162 bf162;

// ---------------- scratch (allocation-free rule: __device__ globals) ----------------
__device__ __align__(256) float g_qkv [(size_t)MTOK * 3 * INNERD];   // fp32 (V region used)
__device__ __align__(256) float g_att [(size_t)MTOK * SQ];           // 64 MB fp32
__device__ __align__(256) bf16  g_x2  [(size_t)MTOK * 3 * DIMM];     // A-style split of x
__device__ __align__(256) bf16  g_q2  [(size_t)MTOK * 3 * INNERD];   // A-style split of Q
__device__ __align__(256) bf16  g_k2  [(size_t)MTOK * 3 * INNERD];   // B-style split of K
__device__ __align__(256) bf16  g_v2  [(size_t)NB * INNERD * 3 * SQ];// B-style transposed V
__device__ __align__(256) bf16  g_at2 [(size_t)MTOK * 3 * SQ];       // A-style split of attn
__device__ __align__(256) bf16  g_ao2 [(size_t)MTOK * 3 * INNERD];   // A-style split of attn@V
__device__ __align__(256) bf16  g_wq2 [(size_t)(3 * INNERD) * (3 * DIMM)]; // [3072, 3072]
__device__ __align__(256) bf16  g_wo2 [(size_t)DIMM * 3 * INNERD];   // [1024, 3072]

// ---------------- helpers ----------------
__device__ __forceinline__ uint32_t smem_u32(const void* p) {
    uint32_t a;
    asm("{ .reg .u64 t; cvta.to.shared.u64 t, %1; cvt.u32.u64 %0, t; }" : "=r"(a) : "l"(p));
    return a;
}
__device__ __forceinline__ void cpa16(uint32_t dst, const void* src) {
    asm volatile("cp.async.cg.shared.global [%0], [%1], 16;" :: "r"(dst), "l"(src));
}
__device__ __forceinline__ void cpa_commit() { asm volatile("cp.async.commit_group;"); }
__device__ __forceinline__ void cpa_wait1()  { asm volatile("cp.async.wait_group 1;" ::: "memory"); }

__device__ __forceinline__ void mma16(float* c, const unsigned* a, unsigned b0, unsigned b1) {
    asm volatile(
        "mma.sync.aligned.m16n8k16.row.col.f32.bf16.bf16.f32 "
        "{%0,%1,%2,%3}, {%4,%5,%6,%7}, {%8,%9}, {%0,%1,%2,%3};\n"
        : "+f"(c[0]), "+f"(c[1]), "+f"(c[2]), "+f"(c[3])
        : "r"(a[0]), "r"(a[1]), "r"(a[2]), "r"(a[3]), "r"(b0), "r"(b1));
}
__device__ __forceinline__ void ldsm4(uint32_t addr, unsigned* r) {
    asm volatile("ldmatrix.sync.aligned.m8n8.x4.shared.b16 {%0,%1,%2,%3}, [%4];"
        : "=r"(r[0]), "=r"(r[1]), "=r"(r[2]), "=r"(r[3]) : "r"(addr));
}
// swizzled byte offset in a [rows][64 bytes] tile, 16B-group q in 0..3
__device__ __forceinline__ int sw64(int row, int q) {
    return row * 64 + ((((unsigned)q) ^ (((unsigned)row >> 1) & 3)) << 4);
}
__device__ __forceinline__ void splitf2(float x, float y, bf162& h, bf162& l) {
    h = __floats2bfloat162_rn(x, y);
    l = __floats2bfloat162_rn(x - __low2float(h), y - __high2float(h));
}

// ---------------- plain bf16 NT GEMM, cp.async 3-stage pipeline ----------------
// C = alpha * A @ B^T (+bias)   A [M,Kp] bf16 ld lda, B [N,Kp] bf16 ld ldb.
// EPI 0: fp32 C.
// EPI 1: bf16 split A-style output [h | l | h] with segment segN.
// EPI 2: QKV fused: n-region 0 -> C2 (q2, [h|l|h]); region 1 -> C3 (k2, [h|h|l]);
//        region 2 -> fp32 C (V only).  segN = 1024.
// CTA 128x128, KC=32, 128 threads = 4 warps (2m x 2n), warp tile 64x64.
template <int EPI>
__global__ __launch_bounds__(128, 2)
void gemm_nt(const bf16* __restrict__ A, const bf16* __restrict__ B,
             float* __restrict__ C, bf16* __restrict__ C2, bf16* __restrict__ C3,
             const float* __restrict__ bias,
             int Kp, int lda, int ldb, int ldc, int segN,
             long long bA, long long bB, long long bC, float alpha)
{
    __shared__ __align__(128) char sA[3 * 8192];
    __shared__ __align__(128) char sB[3 * 8192];
    const uint32_t uA = smem_u32(sA), uB = smem_u32(sB);

    const int tid = threadIdx.x;
    const int m0 = blockIdx.y * 128, n0 = blockIdx.x * 128;
    A += (long long)blockIdx.z * bA;
    B += (long long)blockIdx.z * bB;

    const int warp = tid >> 5, lane = tid & 31;
    const int wm = warp >> 1, wn = warp & 1;

    // fill mapping: row = (tid>>2) + 32*i, q = tid&3  (conflict-free phases)
    const int frow = tid >> 2;
    const int fq   = tid & 3;

    const bf16* pA[4]; const bf16* pB[4];
    uint32_t oX[4];
    #pragma unroll
    for (int i = 0; i < 4; i++) {
        int r = frow + i * 32;
        pA[i] = A + (long long)(m0 + r) * lda + 8 * fq;
        pB[i] = B + (long long)(n0 + r) * ldb + 8 * fq;
        oX[i] = sw64(r, fq);
    }

    auto fill_to = [&](uint32_t da, uint32_t db) {
        #pragma unroll
        for (int i = 0; i < 4; i++) cpa16(da + oX[i], pA[i]);
        #pragma unroll
        for (int i = 0; i < 4; i++) cpa16(db + oX[i], pB[i]);
        cpa_commit();
        #pragma unroll
        for (int i = 0; i < 4; i++) { pA[i] += 32; pB[i] += 32; }
    };

    // ldmatrix components
    const int l15 = lane & 15;
    const int klh = lane >> 4;                    // k-half of k16 (0/1)
    const int sx  = ((l15 >> 1) & 3) << 4;        // swizzle XOR
    const int rA  = (wm * 64 + l15) * 64;
    const int rB  = (wn * 64 + l15) * 64;
    const int xo0 = (klh << 4) ^ sx;              // ks = 0
    const int xo1 = ((2 + klh) << 4) ^ sx;        // ks = 1

    float acc[4][8][4] = {};
    unsigned fA0[4][4], fB0[4][4], fA1[4][4], fB1[4][4];

    const int nch = Kp >> 5;    // divisible by 3 for all our shapes

    // Preamble: fill stages 0,1; wait stage 0; load chunk-0 ks0 fragments.
    fill_to(uA, uB);
    fill_to(uA + 8192, uB + 8192);
    cpa_wait1();
    __syncthreads();
    #pragma unroll
    for (int p = 0; p < 4; p++) ldsm4(uB + rB + p * 1024 + xo0, fB0[p]);
    #pragma unroll
    for (int mi = 0; mi < 4; mi++) ldsm4(uA + rA + mi * 1024 + xo0, fA0[mi]);

    // One chunk: a0/b0 = current stage, a1/b1 = next stage, a2/b2 = fill target.
    // cpa_wait hoisted between the two mma halves: data for stage c+1 was issued
    // two chunks ago, so the wait is ~free there and leaves only sync+ldsm serial.
    auto step = [&](uint32_t a0, uint32_t b0, uint32_t a1, uint32_t b1,
                    uint32_t a2, uint32_t b2, int c) {
        if (c + 2 < nch) fill_to(a2, b2);
        else             cpa_commit();
        #pragma unroll
        for (int p = 0; p < 4; p++) ldsm4(b0 + rB + p * 1024 + xo1, fB1[p]);
        #pragma unroll
        for (int mi = 0; mi < 4; mi++) ldsm4(a0 + rA + mi * 1024 + xo1, fA1[mi]);
        #pragma unroll
        for (int mi = 0; mi < 4; mi++)
            #pragma unroll
            for (int p = 0; p < 4; p++) {
                mma16(acc[mi][2 * p    ], fA0[mi], fB0[p][0], fB0[p][2]);
                mma16(acc[mi][2 * p + 1], fA0[mi], fB0[p][1], fB0[p][3]);
            }
        cpa_wait1();                 // mid-stream: stage c+1 almost surely arrived
        #pragma unroll
        for (int mi = 0; mi < 4; mi++)
            #pragma unroll
            for (int p = 0; p < 4; p++) {
                mma16(acc[mi][2 * p    ], fA1[mi], fB1[p][0], fB1[p][2]);
                mma16(acc[mi][2 * p + 1], fA1[mi], fB1[p][1], fB1[p][3]);
            }
        __syncthreads();
        #pragma unroll
        for (int p = 0; p < 4; p++) ldsm4(b1 + rB + p * 1024 + xo0, fB0[p]);
        #pragma unroll
        for (int mi = 0; mi < 4; mi++) ldsm4(a1 + rA + mi * 1024 + xo0, fA0[mi]);
    };

    for (int c = 0; c < nch; c += 3) {
        step(uA,         uB,         uA + 8192,  uB + 8192,  uA + 16384, uB + 16384, c);
        step(uA + 8192,  uB + 8192,  uA + 16384, uB + 16384, uA,         uB,         c + 1);
        step(uA + 16384, uB + 16384, uA,         uB,         uA + 8192,  uB + 8192,  c + 2);
    }

    // ---- epilogue ----
    const int gid = lane >> 2, tig = lane & 3;
    if (EPI == 0) {
        C += (long long)blockIdx.z * bC;
        #pragma unroll
        for (int mi = 0; mi < 4; mi++) {
            #pragma unroll
            for (int ni = 0; ni < 8; ni++) {
                const int col  = n0 + wn * 64 + ni * 8 + 2 * tig;
                const int row0 = m0 + wm * 64 + mi * 16 + gid;
                float b0v = bias ? bias[col]     : 0.f;
                float b1v = bias ? bias[col + 1] : 0.f;
                float2 v0 = make_float2(acc[mi][ni][0] * alpha + b0v,
                                        acc[mi][ni][1] * alpha + b1v);
                float2 v1 = make_float2(acc[mi][ni][2] * alpha + b0v,
                                        acc[mi][ni][3] * alpha + b1v);
                *(float2*)(C + (long long)row0 * ldc + col)       = v0;
                *(float2*)(C + (long long)(row0 + 8) * ldc + col) = v1;
            }
        }
    } else if (EPI == 1) {
        C2 += (long long)blockIdx.z * bC;
        #pragma unroll
        for (int mi = 0; mi < 4; mi++) {
            #pragma unroll
            for (int ni = 0; ni < 8; ni++) {
                const int col  = n0 + wn * 64 + ni * 8 + 2 * tig;
                const int row0 = m0 + wm * 64 + mi * 16 + gid;
                bf162 h2, l2;
                splitf2(acc[mi][ni][0], acc[mi][ni][1], h2, l2);
                bf16* p0 = C2 + (long long)row0 * ldc + col;
                *(bf162*)p0            = h2;
                *(bf162*)(p0 + segN)   = l2;
                *(bf162*)(p0 + 2*segN) = h2;
                splitf2(acc[mi][ni][2], acc[mi][ni][3], h2, l2);
                bf16* p1 = C2 + (long long)(row0 + 8) * ldc + col;
                *(bf162*)p1            = h2;
                *(bf162*)(p1 + segN)   = l2;
                *(bf162*)(p1 + 2*segN) = h2;
            }
        }
    } else {                       // EPI == 2: fused QKV epilogue
        const int reg = n0 >> 10;  // 0 = Q, 1 = K, 2 = V (uniform per block)
        if (reg == 2) {
            #pragma unroll
            for (int mi = 0; mi < 4; mi++) {
                #pragma unroll
                for (int ni = 0; ni < 8; ni++) {
                    const int col  = n0 + wn * 64 + ni * 8 + 2 * tig;
                    const int row0 = m0 + wm * 64 + mi * 16 + gid;
                    *(float2*)(C + (long long)row0 * ldc + col) =
                        make_float2(acc[mi][ni][0], acc[mi][ni][1]);
                    *(float2*)(C + (long long)(row0 + 8) * ldc + col) =
                        make_float2(acc[mi][ni][2], acc[mi][ni][3]);
                }
            }
        } else {
            bf16* base = (reg == 0) ? C2 : C3;
            #pragma unroll
            for (int mi = 0; mi < 4; mi++) {
                #pragma unroll
                for (int ni = 0; ni < 8; ni++) {
                    const int cloc = (n0 - (reg << 10)) + wn * 64 + ni * 8 + 2 * tig;
                    const int row0 = m0 + wm * 64 + mi * 16 + gid;
                    bf162 h2, l2;
                    splitf2(acc[mi][ni][0], acc[mi][ni][1], h2, l2);
                    bf16* p0 = base + (long long)row0 * ldc + cloc;
                    *(bf162*)p0 = h2;
                    if (reg == 0) { *(bf162*)(p0 + segN) = l2; *(bf162*)(p0 + 2*segN) = h2; }
                    else          { *(bf162*)(p0 + segN) = h2; *(bf162*)(p0 + 2*segN) = l2; }
                    splitf2(acc[mi][ni][2], acc[mi][ni][3], h2, l2);
                    bf16* p1 = base + (long long)(row0 + 8) * ldc + cloc;
                    *(bf162*)p1 = h2;
                    if (reg == 0) { *(bf162*)(p1 + segN) = l2; *(bf162*)(p1 + 2*segN) = h2; }
                    else          { *(bf162*)(p1 + segN) = h2; *(bf162*)(p1 + 2*segN) = l2; }
                }
            }
        }
    }
}

// ---------------- split kernels ----------------
// Row-major split: in fp32 [R,C] (ld ldin) -> out bf16 [R,3C]. A-style [h|l|h].
__global__ __launch_bounds__(256)
void split_rm_a(const float* __restrict__ in, bf16* __restrict__ out, int C, int ldin)
{
    const int r = blockIdx.y;
    const int j = (blockIdx.x * 256 + threadIdx.x) * 2;
    float2 v = *(const float2*)(in + (long long)r * ldin + j);
    bf162 h2, l2;
    splitf2(v.x, v.y, h2, l2);
    bf16* o = out + (long long)r * 3 * C + j;
    *(bf162*)o           = h2;
    *(bf162*)(o + C)     = l2;
    *(bf162*)(o + 2 * C) = h2;
}

// Transpose split (B-style): in fp32 [Krows, N] (ld ldin) -> out bf16 [N, 3*Kd].
__global__ __launch_bounds__(256)
void split_tr(const float* __restrict__ in, bf16* __restrict__ out,
              int ldin, int Kd, long long bIn, long long bOut)
{
    __shared__ float t[32][33];
    in  += (long long)blockIdx.z * bIn;
    out += (long long)blockIdx.z * bOut;
    const int k0 = blockIdx.y * 32, nn0 = blockIdx.x * 32;
    const int tx = threadIdx.x & 31, ty = threadIdx.x >> 5;
    #pragma unroll
    for (int i = 0; i < 4; i++)
        t[ty + 8 * i][tx] = in[(long long)(k0 + ty + 8 * i) * ldin + nn0 + tx];
    __syncthreads();
    #pragma unroll
    for (int i = 0; i < 4; i++) {
        float v = t[tx][ty + 8 * i];
        bf16 h = __float2bfloat16(v);
        bf16 l = __float2bfloat16(v - __bfloat162float(h));
        bf16* o = out + (long long)(nn0 + ty + 8 * i) * (3 * Kd) + k0 + tx;
        o[0] = h; o[Kd] = h; o[2 * Kd] = l;
    }
}

// ---------------- softmax + A-style split (fp32 [8192,2048] -> bf16 [8192,6144]) ----------------
__global__ __launch_bounds__(256)
void softmax_split(const float* __restrict__ att, bf16* __restrict__ out)
{
    const long long r = blockIdx.x;
    const float* row = att + r * 2048;
    bf16* orow = out + r * 6144;
    const int t = threadIdx.x;
    float2 v[4];
    float mx = -1e30f;
    #pragma unroll
    for (int j = 0; j < 4; j++) {
        v[j] = *(const float2*)(row + 2 * (t + j * 256));
        mx = fmaxf(mx, fmaxf(v[j].x, v[j].y));
    }
    __shared__ float red[256];
    red[t] = mx; __syncthreads();
    for (int s = 128; s > 0; s >>= 1) {
        if (t < s) red[t] = fmaxf(red[t], red[t + s]);
        __syncthreads();
    }
    mx = red[0]; __syncthreads();
    float sum = 0.f;
    #pragma unroll
    for (int j = 0; j < 4; j++) {
        v[j].x = __expf(v[j].x - mx);
        v[j].y = __expf(v[j].y - mx);
        sum += v[j].x + v[j].y;
    }
    red[t] = sum; __syncthreads();
    for (int s = 128; s > 0; s >>= 1) {
        if (t < s) red[t] += red[t + s];
        __syncthreads();
    }
    const float inv = 1.f / red[0];
    #pragma unroll
    for (int j = 0; j < 4; j++) {
        const int idx = 2 * (t + j * 256);
        bf162 h2, l2;
        splitf2(v[j].x * inv, v[j].y * inv, h2, l2);
        *(bf162*)(orow + idx)        = h2;
        *(bf162*)(orow + 2048 + idx) = l2;
        *(bf162*)(orow + 4096 + idx) = h2;
    }
}

// ---------------- launch ----------------
extern "C" void kernel_launch(void* const* d_in, const int* in_sizes, int n_in,
                              void* d_out, int out_size)
{
    const float* x    = (const float*)d_in[0];   // [4, 2048, 1024]
    const float* Wqkv = (const float*)d_in[1];   // [1024, 3072]
    const float* Wout = (const float*)d_in[2];   // [1024, 1024]
    const float* bout = (const float*)d_in[3];   // [1024]
    float* out = (float*)d_out;                  // [4, 2048, 1024]

    float *qkv, *att;
    bf16 *x2, *q2, *k2, *v2, *at2, *ao2, *wq2, *wo2;
    cudaGetSymbolAddress((void**)&qkv, g_qkv);
    cudaGetSymbolAddress((void**)&att, g_att);
    cudaGetSymbolAddress((void**)&x2,  g_x2);
    cudaGetSymbolAddress((void**)&q2,  g_q2);
    cudaGetSymbolAddress((void**)&k2,  g_k2);
    cudaGetSymbolAddress((void**)&v2,  g_v2);
    cudaGetSymbolAddress((void**)&at2, g_at2);
    cudaGetSymbolAddress((void**)&ao2, g_ao2);
    cudaGetSymbolAddress((void**)&wq2, g_wq2);
    cudaGetSymbolAddress((void**)&wo2, g_wo2);

    // 0) operand splits of the inputs
    split_rm_a<<<dim3(DIMM / 512, MTOK), 256>>>(x, x2, DIMM, DIMM);
    split_tr<<<dim3(3 * INNERD / 32, DIMM / 32, 1), 256>>>(Wqkv, wq2, 3 * INNERD, DIMM, 0, 0);
    split_tr<<<dim3(DIMM / 32, INNERD / 32, 1), 256>>>(Wout, wo2, DIMM, INNERD, 0, 0);

    // 1) qkv = x @ Wqkv  (M=8192, N=3072, K'=3072) — fused epilogue:
    //    Q cols -> q2 split, K cols -> k2 split, V cols -> fp32 qkv.
    gemm_nt<2><<<dim3(3 * INNERD / 128, MTOK / 128, 1), 128>>>(
        x2, wq2, qkv, q2, k2, nullptr,
        3 * DIMM, 3 * DIMM, 3 * DIMM, 3 * INNERD, 1024, 0, 0, 0, 1.f);

    // 2) transpose-split V from qkv's V region
    split_tr<<<dim3(INNERD / 32, SQ / 32, NB), 256>>>(
        qkv + 2048, v2, 3 * INNERD, SQ,
        (long long)SQ * 3 * INNERD, (long long)INNERD * 3 * SQ);

    // 3) att = 0.125 * Q @ K^T   (per batch, M=N=2048, K'=3072)
    gemm_nt<0><<<dim3(SQ / 128, SQ / 128, NB), 128>>>(
        q2, k2, att, nullptr, nullptr, nullptr,
        3 * INNERD, 3 * INNERD, 3 * INNERD, SQ, 0,
        (long long)SQ * 3 * INNERD, (long long)SQ * 3 * INNERD,
        (long long)SQ * SQ, 0.125f);

    // 4) softmax rows + A-style split
    softmax_split<<<MTOK, 256>>>(att, at2);

    // 5) ao2 = split(attn @ V)   (per batch, M=2048, N=1024, K'=6144; split epilogue)
    gemm_nt<1><<<dim3(INNERD / 128, SQ / 128, NB), 128>>>(
        at2, v2, nullptr, ao2, nullptr, nullptr,
        3 * SQ, 3 * SQ, 3 * SQ, 3 * INNERD, INNERD,
        (long long)SQ * 3 * SQ, (long long)INNERD * 3 * SQ,
        (long long)SQ * 3 * INNERD, 1.f);

    // 6) out = ao @ Wout + bias  (M=8192, N=1024, K'=3072)
    gemm_nt<0><<<dim3(DIMM / 128, MTOK / 128, 1), 128>>>(
        ao2, wo2, out, nullptr, nullptr, bout,
        3 * INNERD, 3 * INNERD, 3 * INNERD, DIMM, 0, 0, 0, 0, 1.f);
}

// round 17
// speedup vs baseline: 1.8563x; 1.1476x over previous
#include <cuda_runtime.h>
#include <cuda_bf16.h>
#include <cuda_fp16.h>
#include <cstdint>
#include <math.h>

// Problem constants
#define NB     4
#define SQ     2048
#define DIMM   1024
#define INNERD 1024
#define MTOK   (NB * SQ)          // 8192

typedef __nv_bfloat16  bf16;
typedef __nv_bfloat162 bf162;

// ---------------- scratch (allocation-free rule: __device__ globals) ----------------
__device__ __align__(256) float  g_qkv [(size_t)MTOK * 3 * INNERD];   // fp32 (V region used)
__device__ __align__(256) float  g_att [(size_t)MTOK * SQ];           // 64 MB fp32
__device__ __align__(256) bf16   g_x2  [(size_t)MTOK * 3 * DIMM];     // A-split of x [h|l|h]
__device__ __align__(256) bf16   g_q2  [(size_t)MTOK * 3 * INNERD];   // A-split of Q
__device__ __align__(256) bf16   g_k2  [(size_t)MTOK * 3 * INNERD];   // B-split of K
__device__ __align__(256) bf16   g_wq2 [(size_t)(3 * INNERD) * (3 * DIMM)]; // [3072, 3072]
// fp16 2-term operands for the post-softmax path
__device__ __align__(256) __half g_at2h[(size_t)MTOK * 2 * SQ];       // attn [h|l]  [8192,4096]
__device__ __align__(256) __half g_v2h [(size_t)NB * INNERD * 2 * SQ];// V^T  [h|h]  [4x1024,4096]
__device__ __align__(256) __half g_ao2h[(size_t)MTOK * 2 * INNERD];   // ao   [h|l]  [8192,2048]
__device__ __align__(256) __half g_wo2h[(size_t)DIMM * 2 * INNERD];   // Wout^T [h|h] [1024,2048]

// ---------------- helpers ----------------
__device__ __forceinline__ uint32_t smem_u32(const void* p) {
    uint32_t a;
    asm("{ .reg .u64 t; cvta.to.shared.u64 t, %1; cvt.u32.u64 %0, t; }" : "=r"(a) : "l"(p));
    return a;
}
__device__ __forceinline__ void cpa16(uint32_t dst, const void* src) {
    asm volatile("cp.async.cg.shared.global [%0], [%1], 16;" :: "r"(dst), "l"(src));
}
__device__ __forceinline__ void cpa_commit() { asm volatile("cp.async.commit_group;"); }
__device__ __forceinline__ void cpa_wait1()  { asm volatile("cp.async.wait_group 1;" ::: "memory"); }

template <int FP16>
__device__ __forceinline__ void mma16(float* c, const unsigned* a, unsigned b0, unsigned b1) {
    if (FP16)
        asm volatile(
            "mma.sync.aligned.m16n8k16.row.col.f32.f16.f16.f32 "
            "{%0,%1,%2,%3}, {%4,%5,%6,%7}, {%8,%9}, {%0,%1,%2,%3};\n"
            : "+f"(c[0]), "+f"(c[1]), "+f"(c[2]), "+f"(c[3])
            : "r"(a[0]), "r"(a[1]), "r"(a[2]), "r"(a[3]), "r"(b0), "r"(b1));
    else
        asm volatile(
            "mma.sync.aligned.m16n8k16.row.col.f32.bf16.bf16.f32 "
            "{%0,%1,%2,%3}, {%4,%5,%6,%7}, {%8,%9}, {%0,%1,%2,%3};\n"
            : "+f"(c[0]), "+f"(c[1]), "+f"(c[2]), "+f"(c[3])
            : "r"(a[0]), "r"(a[1]), "r"(a[2]), "r"(a[3]), "r"(b0), "r"(b1));
}
__device__ __forceinline__ void ldsm4(uint32_t addr, unsigned* r) {
    asm volatile("ldmatrix.sync.aligned.m8n8.x4.shared.b16 {%0,%1,%2,%3}, [%4];"
        : "=r"(r[0]), "=r"(r[1]), "=r"(r[2]), "=r"(r[3]) : "r"(addr));
}
// swizzled byte offset in a [rows][64 bytes] tile, 16B-group q in 0..3
__device__ __forceinline__ int sw64(int row, int q) {
    return row * 64 + ((((unsigned)q) ^ (((unsigned)row >> 1) & 3)) << 4);
}
__device__ __forceinline__ void splitf2(float x, float y, bf162& h, bf162& l) {
    h = __floats2bfloat162_rn(x, y);
    l = __floats2bfloat162_rn(x - __low2float(h), y - __high2float(h));
}
__device__ __forceinline__ void splitf2h(float x, float y, __half2& h, __half2& l) {
    h = __floats2half2_rn(x, y);
    l = __floats2half2_rn(x - __low2float(h), y - __high2float(h));
}

// ---------------- NT GEMM, cp.async 3-stage pipeline ----------------
// C = alpha * A @ B^T (+bias)   A [M,Kp] ld lda, B [N,Kp] ld ldb (2-byte elems).
// FP16: mma dtype. EPI 0: fp32 C.  EPI 1: fp16 2-seg split output [h | l], segN.
// EPI 2: fused QKV: region 0 -> C2 (q2 bf16 [h|l|h]); 1 -> C3 (k2 [h|h|l]); 2 -> fp32 C.
// CTA 128x128, KC=32, 128 threads = 4 warps (2m x 2n), warp tile 64x64.
template <int EPI, int FP16>
__global__ __launch_bounds__(128, 2)
void gemm_nt(const bf16* __restrict__ A, const bf16* __restrict__ B,
             float* __restrict__ C, bf16* __restrict__ C2, bf16* __restrict__ C3,
             const float* __restrict__ bias,
             int Kp, int lda, int ldb, int ldc, int segN,
             long long bA, long long bB, long long bC, float alpha)
{
    __shared__ __align__(128) char sA[3 * 8192];
    __shared__ __align__(128) char sB[3 * 8192];
    const uint32_t uA = smem_u32(sA), uB = smem_u32(sB);

    const int tid = threadIdx.x;
    const int m0 = blockIdx.y * 128, n0 = blockIdx.x * 128;
    A += (long long)blockIdx.z * bA;
    B += (long long)blockIdx.z * bB;

    const int warp = tid >> 5, lane = tid & 31;
    const int wm = warp >> 1, wn = warp & 1;

    // fill mapping: row = (tid>>2) + 32*i, q = tid&3  (conflict-free phases)
    const int frow = tid >> 2;
    const int fq   = tid & 3;

    const bf16* pA[4]; const bf16* pB[4];
    uint32_t oX[4];
    #pragma unroll
    for (int i = 0; i < 4; i++) {
        int r = frow + i * 32;
        pA[i] = A + (long long)(m0 + r) * lda + 8 * fq;
        pB[i] = B + (long long)(n0 + r) * ldb + 8 * fq;
        oX[i] = sw64(r, fq);
    }

    auto fill_to = [&](uint32_t da, uint32_t db) {
        #pragma unroll
        for (int i = 0; i < 4; i++) cpa16(da + oX[i], pA[i]);
        #pragma unroll
        for (int i = 0; i < 4; i++) cpa16(db + oX[i], pB[i]);
        cpa_commit();
        #pragma unroll
        for (int i = 0; i < 4; i++) { pA[i] += 32; pB[i] += 32; }
    };

    // ldmatrix components
    const int l15 = lane & 15;
    const int klh = lane >> 4;                    // k-half of k16 (0/1)
    const int sx  = ((l15 >> 1) & 3) << 4;        // swizzle XOR
    const int rA  = (wm * 64 + l15) * 64;
    const int rB  = (wn * 64 + l15) * 64;
    const int xo0 = (klh << 4) ^ sx;              // ks = 0
    const int xo1 = ((2 + klh) << 4) ^ sx;        // ks = 1

    float acc[4][8][4] = {};
    unsigned fA0[4][4], fB0[4][4], fA1[4][4], fB1[4][4];

    const int nch = Kp >> 5;

    // Preamble: fill stages 0,1; wait stage 0; load chunk-0 ks0 fragments.
    fill_to(uA, uB);
    fill_to(uA + 8192, uB + 8192);
    cpa_wait1();
    __syncthreads();
    #pragma unroll
    for (int p = 0; p < 4; p++) ldsm4(uB + rB + p * 1024 + xo0, fB0[p]);
    #pragma unroll
    for (int mi = 0; mi < 4; mi++) ldsm4(uA + rA + mi * 1024 + xo0, fA0[mi]);

    // One chunk; cpa_wait hoisted mid-stream (stage c+1 issued 2 chunks ago).
    auto step = [&](uint32_t a0, uint32_t b0, uint32_t a1, uint32_t b1,
                    uint32_t a2, uint32_t b2, int c) {
        if (c + 2 < nch) fill_to(a2, b2);
        else             cpa_commit();
        #pragma unroll
        for (int p = 0; p < 4; p++) ldsm4(b0 + rB + p * 1024 + xo1, fB1[p]);
        #pragma unroll
        for (int mi = 0; mi < 4; mi++) ldsm4(a0 + rA + mi * 1024 + xo1, fA1[mi]);
        #pragma unroll
        for (int mi = 0; mi < 4; mi++)
            #pragma unroll
            for (int p = 0; p < 4; p++) {
                mma16<FP16>(acc[mi][2 * p    ], fA0[mi], fB0[p][0], fB0[p][2]);
                mma16<FP16>(acc[mi][2 * p + 1], fA0[mi], fB0[p][1], fB0[p][3]);
            }
        cpa_wait1();
        #pragma unroll
        for (int mi = 0; mi < 4; mi++)
            #pragma unroll
            for (int p = 0; p < 4; p++) {
                mma16<FP16>(acc[mi][2 * p    ], fA1[mi], fB1[p][0], fB1[p][2]);
                mma16<FP16>(acc[mi][2 * p + 1], fA1[mi], fB1[p][1], fB1[p][3]);
            }
        __syncthreads();
        #pragma unroll
        for (int p = 0; p < 4; p++) ldsm4(b1 + rB + p * 1024 + xo0, fB0[p]);
        #pragma unroll
        for (int mi = 0; mi < 4; mi++) ldsm4(a1 + rA + mi * 1024 + xo0, fA0[mi]);
    };

    int c = 0;
    for (; c + 3 <= nch; c += 3) {
        step(uA,         uB,         uA + 8192,  uB + 8192,  uA + 16384, uB + 16384, c);
        step(uA + 8192,  uB + 8192,  uA + 16384, uB + 16384, uA,         uB,         c + 1);
        step(uA + 16384, uB + 16384, uA,         uB,         uA + 8192,  uB + 8192,  c + 2);
    }
    // Tail (nch % 3 chunks); tail stages start at ring position 0.
    if (c < nch)
        step(uA,        uB,        uA + 8192,  uB + 8192,  uA + 16384, uB + 16384, c);
    if (c + 1 < nch)
        step(uA + 8192, uB + 8192, uA + 16384, uB + 16384, uA,         uB,         c + 1);

    // ---- epilogue ----
    const int gid = lane >> 2, tig = lane & 3;
    if (EPI == 0) {
        C += (long long)blockIdx.z * bC;
        #pragma unroll
        for (int mi = 0; mi < 4; mi++) {
            #pragma unroll
            for (int ni = 0; ni < 8; ni++) {
                const int col  = n0 + wn * 64 + ni * 8 + 2 * tig;
                const int row0 = m0 + wm * 64 + mi * 16 + gid;
                float b0v = bias ? bias[col]     : 0.f;
                float b1v = bias ? bias[col + 1] : 0.f;
                float2 v0 = make_float2(acc[mi][ni][0] * alpha + b0v,
                                        acc[mi][ni][1] * alpha + b1v);
                float2 v1 = make_float2(acc[mi][ni][2] * alpha + b0v,
                                        acc[mi][ni][3] * alpha + b1v);
                *(float2*)(C + (long long)row0 * ldc + col)       = v0;
                *(float2*)(C + (long long)(row0 + 8) * ldc + col) = v1;
            }
        }
    } else if (EPI == 1) {
        __half* H = (__half*)C2 + (long long)blockIdx.z * bC;
        #pragma unroll
        for (int mi = 0; mi < 4; mi++) {
            #pragma unroll
            for (int ni = 0; ni < 8; ni++) {
                const int col  = n0 + wn * 64 + ni * 8 + 2 * tig;
                const int row0 = m0 + wm * 64 + mi * 16 + gid;
                __half2 h2, l2;
                splitf2h(acc[mi][ni][0], acc[mi][ni][1], h2, l2);
                __half* p0 = H + (long long)row0 * ldc + col;
                *(__half2*)p0          = h2;
                *(__half2*)(p0 + segN) = l2;
                splitf2h(acc[mi][ni][2], acc[mi][ni][3], h2, l2);
                __half* p1 = H + (long long)(row0 + 8) * ldc + col;
                *(__half2*)p1          = h2;
                *(__half2*)(p1 + segN) = l2;
            }
        }
    } else {                       // EPI == 2: fused QKV epilogue (bf16 3-term)
        const int reg = n0 >> 10;  // 0 = Q, 1 = K, 2 = V (uniform per block)
        if (reg == 2) {
            #pragma unroll
            for (int mi = 0; mi < 4; mi++) {
                #pragma unroll
                for (int ni = 0; ni < 8; ni++) {
                    const int col  = n0 + wn * 64 + ni * 8 + 2 * tig;
                    const int row0 = m0 + wm * 64 + mi * 16 + gid;
                    *(float2*)(C + (long long)row0 * ldc + col) =
                        make_float2(acc[mi][ni][0], acc[mi][ni][1]);
                    *(float2*)(C + (long long)(row0 + 8) * ldc + col) =
                        make_float2(acc[mi][ni][2], acc[mi][ni][3]);
                }
            }
        } else {
            bf16* base = (reg == 0) ? C2 : C3;
            #pragma unroll
            for (int mi = 0; mi < 4; mi++) {
                #pragma unroll
                for (int ni = 0; ni < 8; ni++) {
                    const int cloc = (n0 - (reg << 10)) + wn * 64 + ni * 8 + 2 * tig;
                    const int row0 = m0 + wm * 64 + mi * 16 + gid;
                    bf162 h2, l2;
                    splitf2(acc[mi][ni][0], acc[mi][ni][1], h2, l2);
                    bf16* p0 = base + (long long)row0 * ldc + cloc;
                    *(bf162*)p0 = h2;
                    if (reg == 0) { *(bf162*)(p0 + segN) = l2; *(bf162*)(p0 + 2*segN) = h2; }
                    else          { *(bf162*)(p0 + segN) = h2; *(bf162*)(p0 + 2*segN) = l2; }
                    splitf2(acc[mi][ni][2], acc[mi][ni][3], h2, l2);
                    bf16* p1 = base + (long long)(row0 + 8) * ldc + cloc;
                    *(bf162*)p1 = h2;
                    if (reg == 0) { *(bf162*)(p1 + segN) = l2; *(bf162*)(p1 + 2*segN) = h2; }
                    else          { *(bf162*)(p1 + segN) = h2; *(bf162*)(p1 + 2*segN) = l2; }
                }
            }
        }
    }
}

// ---------------- split kernels ----------------
// Row-major split: in fp32 [R,C] (ld ldin) -> out bf16 [R,3C]. A-style [h|l|h].
__global__ __launch_bounds__(256)
void split_rm_a(const float* __restrict__ in, bf16* __restrict__ out, int C, int ldin)
{
    const int r = blockIdx.y;
    const int j = (blockIdx.x * 256 + threadIdx.x) * 2;
    float2 v = *(const float2*)(in + (long long)r * ldin + j);
    bf162 h2, l2;
    splitf2(v.x, v.y, h2, l2);
    bf16* o = out + (long long)r * 3 * C + j;
    *(bf162*)o           = h2;
    *(bf162*)(o + C)     = l2;
    *(bf162*)(o + 2 * C) = h2;
}

// Transpose split (B-style bf16 3-seg): in fp32 [Krows,N] -> out bf16 [N, 3*Kd].
__global__ __launch_bounds__(256)
void split_tr(const float* __restrict__ in, bf16* __restrict__ out,
              int ldin, int Kd, long long bIn, long long bOut)
{
    __shared__ float t[32][33];
    in  += (long long)blockIdx.z * bIn;
    out += (long long)blockIdx.z * bOut;
    const int k0 = blockIdx.y * 32, nn0 = blockIdx.x * 32;
    const int tx = threadIdx.x & 31, ty = threadIdx.x >> 5;
    #pragma unroll
    for (int i = 0; i < 4; i++)
        t[ty + 8 * i][tx] = in[(long long)(k0 + ty + 8 * i) * ldin + nn0 + tx];
    __syncthreads();
    #pragma unroll
    for (int i = 0; i < 4; i++) {
        float v = t[tx][ty + 8 * i];
        bf16 h = __float2bfloat16(v);
        bf16 l = __float2bfloat16(v - __bfloat162float(h));
        bf16* o = out + (long long)(nn0 + ty + 8 * i) * (3 * Kd) + k0 + tx;
        o[0] = h; o[Kd] = h; o[2 * Kd] = l;
    }
}

// Transpose fp16 duplicate (B-style [h|h]): in fp32 [Krows,N] -> out half [N, 2*Kd].
__global__ __launch_bounds__(256)
void split_tr_h(const float* __restrict__ in, __half* __restrict__ out,
                int ldin, int Kd, long long bIn, long long bOut)
{
    __shared__ float t[32][33];
    in  += (long long)blockIdx.z * bIn;
    out += (long long)blockIdx.z * bOut;
    const int k0 = blockIdx.y * 32, nn0 = blockIdx.x * 32;
    const int tx = threadIdx.x & 31, ty = threadIdx.x >> 5;
    #pragma unroll
    for (int i = 0; i < 4; i++)
        t[ty + 8 * i][tx] = in[(long long)(k0 + ty + 8 * i) * ldin + nn0 + tx];
    __syncthreads();
    #pragma unroll
    for (int i = 0; i < 4; i++) {
        __half h = __float2half_rn(t[tx][ty + 8 * i]);
        __half* o = out + (long long)(nn0 + ty + 8 * i) * (2 * Kd) + k0 + tx;
        o[0] = h; o[Kd] = h;
    }
}

// ---------------- softmax + fp16 [h|l] split (fp32 [8192,2048] -> half [8192,4096]) ----------------
__global__ __launch_bounds__(256)
void softmax_split(const float* __restrict__ att, __half* __restrict__ out)
{
    const long long r = blockIdx.x;
    const float* row = att + r * 2048;
    __half* orow = out + r * 4096;
    const int t = threadIdx.x;
    float2 v[4];
    float mx = -1e30f;
    #pragma unroll
    for (int j = 0; j < 4; j++) {
        v[j] = *(const float2*)(row + 2 * (t + j * 256));
        mx = fmaxf(mx, fmaxf(v[j].x, v[j].y));
    }
    __shared__ float red[256];
    red[t] = mx; __syncthreads();
    for (int s = 128; s > 0; s >>= 1) {
        if (t < s) red[t] = fmaxf(red[t], red[t + s]);
        __syncthreads();
    }
    mx = red[0]; __syncthreads();
    float sum = 0.f;
    #pragma unroll
    for (int j = 0; j < 4; j++) {
        v[j].x = __expf(v[j].x - mx);
        v[j].y = __expf(v[j].y - mx);
        sum += v[j].x + v[j].y;
    }
    red[t] = sum; __syncthreads();
    for (int s = 128; s > 0; s >>= 1) {
        if (t < s) red[t] += red[t + s];
        __syncthreads();
    }
    const float inv = 1.f / red[0];
    #pragma unroll
    for (int j = 0; j < 4; j++) {
        const int idx = 2 * (t + j * 256);
        __half2 h2, l2;
        splitf2h(v[j].x * inv, v[j].y * inv, h2, l2);
        *(__half2*)(orow + idx)        = h2;
        *(__half2*)(orow + 2048 + idx) = l2;
    }
}

// ---------------- launch ----------------
extern "C" void kernel_launch(void* const* d_in, const int* in_sizes, int n_in,
                              void* d_out, int out_size)
{
    const float* x    = (const float*)d_in[0];   // [4, 2048, 1024]
    const float* Wqkv = (const float*)d_in[1];   // [1024, 3072]
    const float* Wout = (const float*)d_in[2];   // [1024, 1024]
    const float* bout = (const float*)d_in[3];   // [1024]
    float* out = (float*)d_out;                  // [4, 2048, 1024]

    float *qkv, *att;
    bf16 *x2, *q2, *k2, *wq2;
    __half *at2h, *v2h, *ao2h, *wo2h;
    cudaGetSymbolAddress((void**)&qkv,  g_qkv);
    cudaGetSymbolAddress((void**)&att,  g_att);
    cudaGetSymbolAddress((void**)&x2,   g_x2);
    cudaGetSymbolAddress((void**)&q2,   g_q2);
    cudaGetSymbolAddress((void**)&k2,   g_k2);
    cudaGetSymbolAddress((void**)&wq2,  g_wq2);
    cudaGetSymbolAddress((void**)&at2h, g_at2h);
    cudaGetSymbolAddress((void**)&v2h,  g_v2h);
    cudaGetSymbolAddress((void**)&ao2h, g_ao2h);
    cudaGetSymbolAddress((void**)&wo2h, g_wo2h);

    // 0) operand splits of the inputs
    split_rm_a<<<dim3(DIMM / 512, MTOK), 256>>>(x, x2, DIMM, DIMM);
    split_tr<<<dim3(3 * INNERD / 32, DIMM / 32, 1), 256>>>(Wqkv, wq2, 3 * INNERD, DIMM, 0, 0);
    split_tr_h<<<dim3(DIMM / 32, INNERD / 32, 1), 256>>>(Wout, wo2h, DIMM, INNERD, 0, 0);

    // 1) qkv = x @ Wqkv  (bf16 3-term, M=8192, N=3072, K'=3072) — fused epilogue:
    //    Q cols -> q2 split, K cols -> k2 split, V cols -> fp32 qkv.
    gemm_nt<2, 0><<<dim3(3 * INNERD / 128, MTOK / 128, 1), 128>>>(
        x2, wq2, qkv, q2, k2, nullptr,
        3 * DIMM, 3 * DIMM, 3 * DIMM, 3 * INNERD, 1024, 0, 0, 0, 1.f);

    // 2) transpose-split V (fp16 [h|h]) from qkv's V region
    split_tr_h<<<dim3(INNERD / 32, SQ / 32, NB), 256>>>(
        qkv + 2048, v2h, 3 * INNERD, SQ,
        (long long)SQ * 3 * INNERD, (long long)INNERD * 2 * SQ);

    // 3) att = 0.125 * Q @ K^T   (bf16 3-term, per batch, M=N=2048, K'=3072)
    gemm_nt<0, 0><<<dim3(SQ / 128, SQ / 128, NB), 128>>>(
        q2, k2, att, nullptr, nullptr, nullptr,
        3 * INNERD, 3 * INNERD, 3 * INNERD, SQ, 0,
        (long long)SQ * 3 * INNERD, (long long)SQ * 3 * INNERD,
        (long long)SQ * SQ, 0.125f);

    // 4) softmax rows + fp16 [h|l] split
    softmax_split<<<MTOK, 256>>>(att, at2h);

    // 5) ao2h = split(attn @ V)   (fp16 2-term, per batch, M=2048, N=1024, K'=4096)
    gemm_nt<1, 1><<<dim3(INNERD / 128, SQ / 128, NB), 128>>>(
        (const bf16*)at2h, (const bf16*)v2h, nullptr, (bf16*)ao2h, nullptr, nullptr,
        2 * SQ, 2 * SQ, 2 * SQ, 2 * INNERD, INNERD,
        (long long)SQ * 2 * SQ, (long long)INNERD * 2 * SQ,
        (long long)SQ * 2 * INNERD, 1.f);

    // 6) out = ao @ Wout + bias  (fp16 2-term, M=8192, N=1024, K'=2048)
    gemm_nt<0, 1><<<dim3(DIMM / 128, MTOK / 128, 1), 128>>>(
        (const bf16*)ao2h, (const bf16*)wo2h, out, nullptr, nullptr, bout,
        2 * INNERD, 2 * INNERD, 2 * INNERD, DIMM, 0, 0, 0, 0, 1.f);
}